// round 4
// baseline (speedup 1.0000x reference)
#include <cuda_runtime.h>
#include <math.h>

// Cross-kernel scratch (no allocations allowed).
__device__ float  g_S, g_Irec, g_Rinf, g_A;
__device__ double g_c;        // log2(u), u = 1 - g + beff*S_frozen
__device__ int    g_r;        // row index of the recorded (frozen) state
__device__ int    g_rsplit;   // first row kernel 2 owns (multiple of 4)
__device__ int    g_cut;      // first row of the constant region (multiple of 4), <= steps

#define SMEM_ROWS 4096        // 48 KB buffer; freeze expected at ~290 rows

// ---------------------------------------------------------------------------
// Kernel A: serial scan until S bitwise-frozen; rows buffered in SMEM (STS is
// issue-only, keeping the serial loop near its 8-cyc FMA-chain floor), then
// the whole block copies smem -> gmem coalesced.
//   u = 1-g+beff*S ; nI = I*u ; nS = fma(-beff*I,S,S) ; nR = fma(g,I,R)
// Fallback (no freeze within SMEM_ROWS): finish serially to gmem (always correct).
// ---------------------------------------------------------------------------
__global__ void __launch_bounds__(256, 1)
sir_scan_kernel(const float* __restrict__ x,
                const float* __restrict__ bw,
                const float* __restrict__ gw,
                int steps,
                float* __restrict__ out)
{
    __shared__ float s_rows[SMEM_ROWS * 3];
    __shared__ int   s_nrows;   // rows buffered in smem

    const int tid = threadIdx.x;

    if (tid == 0) {
        float S = x[0], I = x[1], R = x[2];
        const float pop  = __fadd_rn(__fadd_rn(x[0], x[1]), x[2]);
        const float g    = gw[0];
        const float beff = (pop == 1.0f) ? bw[0] : __fdiv_rn(bw[0], pop);
        const float omg  = __fsub_rn(1.0f, g);

        s_rows[0] = S; s_rows[1] = I; s_rows[2] = R;

        int i = 1;
        // Head rows 1..3 so chunks start at i=4.
        for (int h = 0; h < 3 && i < steps; ++h, ++i) {
            float u  = __fmaf_rn(beff, S, omg);
            float v  = __fmul_rn(beff, I);
            float nI = __fmul_rn(I, u);
            float nS = __fmaf_rn(-v, S, S);
            float nR = __fmaf_rn(g, I, R);
            S = nS; I = nI; R = nR;
            s_rows[3*i] = S; s_rows[3*i+1] = I; s_rows[3*i+2] = R;
        }

        bool frozen = false;
        const int cap = (steps < SMEM_ROWS) ? steps : SMEM_ROWS;
        for (; i + 4 <= cap; i += 4) {
            const float S0 = S;
            float r[12];
            #pragma unroll
            for (int k = 0; k < 4; ++k) {
                float u  = __fmaf_rn(beff, S, omg);
                float v  = __fmul_rn(beff, I);
                float nI = __fmul_rn(I, u);
                float nS = __fmaf_rn(-v, S, S);
                float nR = __fmaf_rn(g, I, R);
                S = nS; I = nI; R = nR;
                r[3*k] = S; r[3*k+1] = I; r[3*k+2] = R;
            }
            float4* p = reinterpret_cast<float4*>(s_rows + 3 * i);
            p[0] = make_float4(r[0], r[1],  r[2],  r[3]);
            p[1] = make_float4(r[4], r[5],  r[6],  r[7]);
            p[2] = make_float4(r[8], r[9],  r[10], r[11]);

            if (S == S0) {
                float u = __fmaf_rn(beff, S, omg);
                if (u < 1.0f && u > 0.0f) {   // contracting: S frozen permanently
                    i += 4;                    // rows [0, i) buffered; state = row i-1
                    frozen = true;
                    break;
                }
            }
        }

        if (frozen) {
            const int r_row = i - 1;
            const float  u  = __fmaf_rn(beff, S, omg);
            const double ud = (double)u;
            const double c  = log2(ud);                     // < 0
            const double Ad = (double)g * (double)I / (1.0 - ud);
            const double Rinf = (double)R + Ad;

            double mx = fmax((double)I, Ad);
            if (mx < 1e-300) mx = 1e-300;
            double t_d = (160.0 + log2(mx)) / (-c);
            long long cut_ll = r_row + (long long)t_d + 8;
            long long cut4   = ((cut_ll + 3) / 4) * 4;      // multiple of 4
            if (cut4 < (long long)i) cut4 = i;
            int cut = (cut4 > (long long)steps) ? steps : (int)cut4;

            g_r = r_row; g_rsplit = i; g_cut = cut;
            g_S = S; g_Irec = I; g_A = (float)Ad;
            g_Rinf = (float)Rinf; g_c = c;
            s_nrows = i;
        } else {
            // Fallback: finish serially straight to gmem. Kernel 2 will no-op.
            s_nrows = i;
            for (; i < steps; ++i) {
                float u  = __fmaf_rn(beff, S, omg);
                float v  = __fmul_rn(beff, I);
                float nI = __fmul_rn(I, u);
                float nS = __fmaf_rn(-v, S, S);
                float nR = __fmaf_rn(g, I, R);
                S = nS; I = nI; R = nR;
                out[3*i] = S; out[3*i+1] = I; out[3*i+2] = R;
            }
            g_r = steps - 1; g_rsplit = steps; g_cut = steps;
            g_S = S; g_Irec = I; g_A = 0.0f; g_Rinf = R; g_c = 0.0;
        }
    }

    __syncthreads();

    // Whole block copies the buffered head rows, coalesced float4s.
    const int nelem  = 3 * s_nrows;
    const int count4 = nelem / 4;              // s_nrows is a multiple of 4 (or tiny)
    const float4* src = reinterpret_cast<const float4*>(s_rows);
    float4*       dst = reinterpret_cast<float4*>(out);
    for (int idx = tid; idx < count4; idx += blockDim.x)
        dst[idx] = src[idx];
    for (int e = count4 * 4 + tid; e < nelem; e += blockDim.x)   // tiny-steps remainder
        out[e] = s_rows[e];
}

// ---------------------------------------------------------------------------
// Kernel B (fused): rows [rsplit, cut) closed form, rows [cut, steps) constant.
//   m = k - r ; p = 2^(m*c) ; I = Irec*p ; R = Rinf - A*p ; S = S_frozen
// Both region boundaries are multiples of 4 rows => element offsets are
// multiples of 12 => pure float4 indices, phase = j % 3.
// ---------------------------------------------------------------------------
__global__ void sir_tail_kernel(float* __restrict__ out, int total_elems)
{
    const int start4 = (3 * g_rsplit) / 4;
    const int cut4   = (3 * g_cut) / 4;
    const int n4     = total_elems / 4;

    const int   r    = g_r;
    const float S    = g_S;
    const float Irec = g_Irec;
    const float A    = g_A;
    const float Rinf = g_Rinf;
    const double c   = g_c;

    const float4 p0 = make_float4(S,    0.0f, Rinf, S);
    const float4 p1 = make_float4(0.0f, Rinf, S,    0.0f);
    const float4 p2 = make_float4(Rinf, S,    0.0f, Rinf);

    const int stride = gridDim.x * blockDim.x;
    for (int j = start4 + blockIdx.x * blockDim.x + threadIdx.x; j < n4; j += stride) {
        if (j < cut4) {
            // Transition region: per-element closed form.
            float vals[4];
            #pragma unroll
            for (int t = 0; t < 4; ++t) {
                const int e = 4 * j + t;
                const int k = e / 3;
                const int comp = e - 3 * k;
                const int m = k - r;
                const float p = exp2f((float)((double)m * c));
                vals[t] = (comp == 0) ? S
                        : (comp == 1) ? __fmul_rn(Irec, p)
                                      : __fmaf_rn(-A, p, Rinf);
            }
            reinterpret_cast<float4*>(out)[j] =
                make_float4(vals[0], vals[1], vals[2], vals[3]);
        } else {
            const int ph = j % 3;
            reinterpret_cast<float4*>(out)[j] = (ph == 0) ? p0 : ((ph == 1) ? p1 : p2);
        }
    }

    // Scalar remainder (total_elems % 4 != 0 — not hit for steps = 4M).
    if (blockIdx.x == 0 && threadIdx.x == 0) {
        for (int e = n4 * 4; e < total_elems; ++e) {
            if (e >= 3 * g_rsplit) {
                const int k = e / 3;
                const int comp = e - 3 * k;
                if (k >= g_cut) {
                    out[e] = (comp == 0) ? S : ((comp == 1) ? 0.0f : Rinf);
                } else {
                    const float p = exp2f((float)((double)(k - r) * c));
                    out[e] = (comp == 0) ? S
                           : (comp == 1) ? __fmul_rn(Irec, p)
                                         : __fmaf_rn(-A, p, Rinf);
                }
            }
        }
    }
}

extern "C" void kernel_launch(void* const* d_in, const int* in_sizes, int n_in,
                              void* d_out, int out_size)
{
    const float* x  = (const float*)d_in[0];
    const float* bw = (const float*)d_in[1];
    const float* gw = (const float*)d_in[2];
    float* out = (float*)d_out;

    const int steps = out_size / 3;

    sir_scan_kernel<<<1, 256>>>(x, bw, gw, steps, out);

    const int threads = 256;
    int blocks = (out_size / 4 + threads - 1) / threads;
    if (blocks < 1) blocks = 1;
    sir_tail_kernel<<<blocks, threads>>>(out, out_size);
}